// round 8
// baseline (speedup 1.0000x reference)
#include <cuda_runtime.h>
#include <math.h>

// ---------------------------------------------------------------------------
// RandomProjection: out[b,o] = mean_s( cos(x[b,s,:], p[o,:]) )
//   kernel 1: m = mean_s(x/||x||) (ticket combine) + p-norms + zero(out)
//   kernel 2: register-tiled GEMM, k-split 16, rpn folded into staged p,
//             atomicAdd epilogue
// ---------------------------------------------------------------------------

#define B_     32
#define S_     512
#define D_     768
#define O_     2048
#define EPS_   1e-8f

#define KSPLIT 16
#define KB     48            // k floats per gemm block
#define OTILE  64            // o rows per gemm block
#define NOT_   (O_ / OTILE)  // 32 o-tiles
#define PM     52            // smem pitch (floats): conflict-free

__device__ float g_part[4 * B_ * D_];    // x partials (race-free)
__device__ float g_m[B_ * D_];           // combined mean
__device__ float g_rpn[O_];              // 1/max(||p_o||,eps)
__device__ int   g_ticket[B_];           // kernel1 tickets (zero-init, self-reset)

// ---- packed f32x2 helpers --------------------------------------------------
__device__ __forceinline__ void fma2(unsigned long long& d,
                                     unsigned long long a,
                                     unsigned long long b) {
    asm("fma.rn.f32x2 %0, %1, %2, %3;" : "=l"(d) : "l"(a), "l"(b), "l"(d));
}
__device__ __forceinline__ float unpack_sum(unsigned long long v) {
    float lo, hi;
    asm("mov.b64 {%0, %1}, %2;" : "=f"(lo), "=f"(hi) : "l"(v));
    return lo + hi;
}

// ---------------------------------------------------------------------------
// Kernel 1: blocks 0..127: x normalize+reduce; ticket combine -> g_m.
//           blocks 128..143: p-norms (128 rows each) + zero out-slice.
// ---------------------------------------------------------------------------
__global__ void __launch_bounds__(512, 1)
reduce_x_kernel(const float* __restrict__ x, const float* __restrict__ p,
                float* __restrict__ out) {
    const int warp = threadIdx.x >> 5;
    const int lane = threadIdx.x & 31;

    if (blockIdx.x >= 128) {
        const int blk = blockIdx.x - 128;      // 0..15
        {
            float4* o4 = reinterpret_cast<float4*>(out) + blk * 1024;
            o4[threadIdx.x]       = make_float4(0.f, 0.f, 0.f, 0.f);
            o4[threadIdx.x + 512] = make_float4(0.f, 0.f, 0.f, 0.f);
        }
        const int row0 = blk * 128 + warp * 8;
        #pragma unroll 1
        for (int r = 0; r < 8; r++) {
            const int o = row0 + r;
            const float4* prow = reinterpret_cast<const float4*>(p + (size_t)o * D_);
            float ss = 0.f;
            #pragma unroll
            for (int c = 0; c < 6; c++) {
                const float4 v = prow[lane + 32 * c];
                ss += v.x * v.x + v.y * v.y + v.z * v.z + v.w * v.w;
            }
            #pragma unroll
            for (int off = 16; off > 0; off >>= 1)
                ss += __shfl_xor_sync(0xFFFFFFFFu, ss, off);
            if (lane == 0) g_rpn[o] = 1.0f / fmaxf(sqrtf(ss), EPS_);
        }
        return;
    }

    __shared__ float4 sm[16 * 192];
    __shared__ int is_last;

    const int q = blockIdx.x & 3;
    const int b = blockIdx.x >> 2;

    const float4* base = reinterpret_cast<const float4*>(
        x + ((size_t)b * S_ + (size_t)q * 128 + (size_t)warp * 8) * D_);

    const float inv_S = 1.0f / (float)S_;

    float4 acc[6];
    #pragma unroll
    for (int c = 0; c < 6; c++) acc[c] = make_float4(0.f, 0.f, 0.f, 0.f);

    float4 v[6];
    #pragma unroll
    for (int c = 0; c < 6; c++) v[c] = base[lane + 32 * c];

    #pragma unroll
    for (int r = 0; r < 8; r++) {
        float4 vn[6];
        if (r < 7) {
            #pragma unroll
            for (int c = 0; c < 6; c++)
                vn[c] = base[(r + 1) * 192 + lane + 32 * c];
        }
        float ss = 0.f;
        #pragma unroll
        for (int c = 0; c < 6; c++)
            ss += v[c].x * v[c].x + v[c].y * v[c].y
                + v[c].z * v[c].z + v[c].w * v[c].w;
        #pragma unroll
        for (int off = 16; off > 0; off >>= 1)
            ss += __shfl_xor_sync(0xFFFFFFFFu, ss, off);

        const float scale = inv_S / fmaxf(sqrtf(ss), EPS_);
        #pragma unroll
        for (int c = 0; c < 6; c++) {
            acc[c].x += v[c].x * scale;
            acc[c].y += v[c].y * scale;
            acc[c].z += v[c].z * scale;
            acc[c].w += v[c].w * scale;
        }
        if (r < 7) {
            #pragma unroll
            for (int c = 0; c < 6; c++) v[c] = vn[c];
        }
    }

    #pragma unroll
    for (int c = 0; c < 6; c++)
        sm[warp * 192 + lane + 32 * c] = acc[c];
    __syncthreads();

    if (threadIdx.x < 192) {
        float4 s = sm[threadIdx.x];
        #pragma unroll
        for (int w = 1; w < 16; w++) {
            const float4 t = sm[w * 192 + threadIdx.x];
            s.x += t.x; s.y += t.y; s.z += t.z; s.w += t.w;
        }
        reinterpret_cast<float4*>(g_part)[((q * B_ + b) * 192) + threadIdx.x] = s;
    }

    __threadfence();
    __syncthreads();
    if (threadIdx.x == 0)
        is_last = (atomicAdd(&g_ticket[b], 1) == 3) ? 1 : 0;
    __syncthreads();

    if (is_last) {
        __threadfence();
        if (threadIdx.x < 192) {
            const float4* gp = reinterpret_cast<const float4*>(g_part);
            float4 a  = gp[(0 * B_ + b) * 192 + threadIdx.x];
            const float4 b4 = gp[(1 * B_ + b) * 192 + threadIdx.x];
            const float4 c4 = gp[(2 * B_ + b) * 192 + threadIdx.x];
            const float4 d4 = gp[(3 * B_ + b) * 192 + threadIdx.x];
            a.x += b4.x + c4.x + d4.x;
            a.y += b4.y + c4.y + d4.y;
            a.z += b4.z + c4.z + d4.z;
            a.w += b4.w + c4.w + d4.w;
            reinterpret_cast<float4*>(g_m)[b * 192 + threadIdx.x] = a;
        }
        if (threadIdx.x == 0) g_ticket[b] = 0;
    }
}

// ---------------------------------------------------------------------------
// Kernel 2: register-tiled GEMM, atomicAdd epilogue.
// Grid: 512 = 32 o-tiles x 16 k-splits. Block: 256 threads (~20 KB smem,
// ~5 blocks/SM residency, ~3.5 blocks/SM from grid -> occ ~43%).
// Warp (wb 0..3, wo 0..1): tile 8b x 32o. Lane (bi = l>>3, oj = l&7): 2b x 4o.
// psm is pre-scaled by g_rpn, so accumulators are final -> atomicAdd(out).
// ---------------------------------------------------------------------------
__global__ void __launch_bounds__(256)
gemm_kernel(const float* __restrict__ p, float* __restrict__ out) {
    __shared__ float msm[B_ * PM];      // 32 x 52 floats = 6.7 KB
    __shared__ float psm[OTILE * PM];   // 64 x 52 floats = 13.3 KB

    const int kq  = blockIdx.x & (KSPLIT - 1);
    const int ot  = blockIdx.x / KSPLIT;    // 0..31
    const int tid = threadIdx.x;
    const int k0  = kq * KB;

    // stage m[32][48] (384 float4) and p[ot*64..+64][48]*rpn (768 float4)
    {
        const int i = tid;                      // 0..255 -> first 256 of 384
        const int row = i / 12;
        const int col = (i - row * 12) * 4;
        const float4 v4 = *reinterpret_cast<const float4*>(
            g_m + (size_t)row * D_ + k0 + col);
        *reinterpret_cast<float4*>(&msm[row * PM + col]) = v4;
    }
    if (tid < 128) {
        const int i = tid + 256;                // 256..383
        const int row = i / 12;
        const int col = (i - row * 12) * 4;
        const float4 v4 = *reinterpret_cast<const float4*>(
            g_m + (size_t)row * D_ + k0 + col);
        *reinterpret_cast<float4*>(&msm[row * PM + col]) = v4;
    }
    #pragma unroll
    for (int t = 0; t < 3; t++) {
        const int i   = tid + t * 256;          // 0..767
        const int row = i / 12;
        const int col = (i - row * 12) * 4;
        float4 v4 = *reinterpret_cast<const float4*>(
            p + (size_t)(ot * OTILE + row) * D_ + k0 + col);
        const float rp = g_rpn[ot * OTILE + row];
        v4.x *= rp; v4.y *= rp; v4.z *= rp; v4.w *= rp;
        *reinterpret_cast<float4*>(&psm[row * PM + col]) = v4;
    }
    __syncthreads();

    const int warp = tid >> 5;
    const int lane = tid & 31;
    const int wb = warp >> 1;            // 0..3
    const int wo = warp & 1;             // 0..1
    const int bi = lane >> 3;            // 0..3
    const int oj = lane & 7;             // 0..7

    const float* mb = &msm[(wb * 8 + bi * 2) * PM];
    const float* pb = &psm[(wo * 32 + oj) * PM];

    unsigned long long acc[2][4];
    #pragma unroll
    for (int rr = 0; rr < 2; rr++)
        #pragma unroll
        for (int ss = 0; ss < 4; ss++) acc[rr][ss] = 0ull;

    #pragma unroll
    for (int kk = 0; kk < 12; kk++) {
        const ulonglong2 m0 = *reinterpret_cast<const ulonglong2*>(mb + kk * 4);
        const ulonglong2 m1 = *reinterpret_cast<const ulonglong2*>(mb + PM + kk * 4);
        ulonglong2 pv[4];
        #pragma unroll
        for (int ss = 0; ss < 4; ss++)
            pv[ss] = *reinterpret_cast<const ulonglong2*>(pb + ss * 8 * PM + kk * 4);

        #pragma unroll
        for (int ss = 0; ss < 4; ss++) {
            fma2(acc[0][ss], m0.x, pv[ss].x);
            fma2(acc[0][ss], m0.y, pv[ss].y);
            fma2(acc[1][ss], m1.x, pv[ss].x);
            fma2(acc[1][ss], m1.y, pv[ss].y);
        }
    }

    // epilogue: accumulators already scaled by rpn -> atomicAdd into out
    #pragma unroll
    for (int rr = 0; rr < 2; rr++) {
        const int b = wb * 8 + bi * 2 + rr;
        #pragma unroll
        for (int ss = 0; ss < 4; ss++) {
            const int o = ot * OTILE + wo * 32 + oj + 8 * ss;
            atomicAdd(out + (size_t)b * O_ + o, unpack_sum(acc[rr][ss]));
        }
    }
}

// ---------------------------------------------------------------------------
extern "C" void kernel_launch(void* const* d_in, const int* in_sizes, int n_in,
                              void* d_out, int out_size) {
    const float* x = (const float*)d_in[0];   // [32, 512, 768]
    const float* p = (const float*)d_in[1];   // [2048, 768]
    float*     out = (float*)d_out;           // [32, 2048]

    (void)in_sizes; (void)n_in; (void)out_size;

    reduce_x_kernel<<<128 + 16, 512>>>(x, p, out);
    gemm_kernel<<<NOT_ * KSPLIT, 256>>>(p, out);
}

// round 9
// speedup vs baseline: 1.4896x; 1.4896x over previous
#include <cuda_runtime.h>
#include <math.h>

// ---------------------------------------------------------------------------
// RandomProjection: out[b,o] = mean_s( cos(x[b,s,:], p[o,:]) )
//   kernel 1: m = mean_s(x/||x||) (ticket combine) + p-norms + zero(out)
//   kernel 2: register-tiled GEMM, lane tile 4b x 4o (LDS/fma2 = 0.25),
//             k-split 24, rpn folded into staged p, atomicAdd epilogue
// ---------------------------------------------------------------------------

#define B_     32
#define S_     512
#define D_     768
#define O_     2048
#define EPS_   1e-8f

#define KSPLIT 24
#define KB     32            // k floats per gemm block
#define OTILE  128           // o rows per gemm block
#define NOT_   (O_ / OTILE)  // 16 o-tiles
#define PM     36            // smem pitch (floats): conflict-free

__device__ float g_part[4 * B_ * D_];    // x partials (race-free)
__device__ float g_m[B_ * D_];           // combined mean
__device__ float g_rpn[O_];              // 1/max(||p_o||,eps)
__device__ int   g_ticket[B_];           // kernel1 tickets (zero-init, self-reset)

// ---- packed f32x2 helpers --------------------------------------------------
__device__ __forceinline__ void fma2(unsigned long long& d,
                                     unsigned long long a,
                                     unsigned long long b) {
    asm("fma.rn.f32x2 %0, %1, %2, %3;" : "=l"(d) : "l"(a), "l"(b), "l"(d));
}
__device__ __forceinline__ float unpack_sum(unsigned long long v) {
    float lo, hi;
    asm("mov.b64 {%0, %1}, %2;" : "=f"(lo), "=f"(hi) : "l"(v));
    return lo + hi;
}

// ---------------------------------------------------------------------------
// Kernel 1: blocks 0..127: x normalize+reduce; ticket combine -> g_m.
//           blocks 128..143: p-norms (128 rows each) + zero out-slice.
// ---------------------------------------------------------------------------
__global__ void __launch_bounds__(512, 1)
reduce_x_kernel(const float* __restrict__ x, const float* __restrict__ p,
                float* __restrict__ out) {
    const int warp = threadIdx.x >> 5;
    const int lane = threadIdx.x & 31;

    if (blockIdx.x >= 128) {
        const int blk = blockIdx.x - 128;      // 0..15
        {
            float4* o4 = reinterpret_cast<float4*>(out) + blk * 1024;
            o4[threadIdx.x]       = make_float4(0.f, 0.f, 0.f, 0.f);
            o4[threadIdx.x + 512] = make_float4(0.f, 0.f, 0.f, 0.f);
        }
        const int row0 = blk * 128 + warp * 8;
        #pragma unroll 1
        for (int r = 0; r < 8; r++) {
            const int o = row0 + r;
            const float4* prow = reinterpret_cast<const float4*>(p + (size_t)o * D_);
            float ss = 0.f;
            #pragma unroll
            for (int c = 0; c < 6; c++) {
                const float4 v = prow[lane + 32 * c];
                ss += v.x * v.x + v.y * v.y + v.z * v.z + v.w * v.w;
            }
            #pragma unroll
            for (int off = 16; off > 0; off >>= 1)
                ss += __shfl_xor_sync(0xFFFFFFFFu, ss, off);
            if (lane == 0) g_rpn[o] = 1.0f / fmaxf(sqrtf(ss), EPS_);
        }
        return;
    }

    __shared__ float4 sm[16 * 192];
    __shared__ int is_last;

    const int q = blockIdx.x & 3;
    const int b = blockIdx.x >> 2;

    const float4* base = reinterpret_cast<const float4*>(
        x + ((size_t)b * S_ + (size_t)q * 128 + (size_t)warp * 8) * D_);

    const float inv_S = 1.0f / (float)S_;

    float4 acc[6];
    #pragma unroll
    for (int c = 0; c < 6; c++) acc[c] = make_float4(0.f, 0.f, 0.f, 0.f);

    float4 v[6];
    #pragma unroll
    for (int c = 0; c < 6; c++) v[c] = base[lane + 32 * c];

    #pragma unroll
    for (int r = 0; r < 8; r++) {
        float4 vn[6];
        if (r < 7) {
            #pragma unroll
            for (int c = 0; c < 6; c++)
                vn[c] = base[(r + 1) * 192 + lane + 32 * c];
        }
        float ss = 0.f;
        #pragma unroll
        for (int c = 0; c < 6; c++)
            ss += v[c].x * v[c].x + v[c].y * v[c].y
                + v[c].z * v[c].z + v[c].w * v[c].w;
        #pragma unroll
        for (int off = 16; off > 0; off >>= 1)
            ss += __shfl_xor_sync(0xFFFFFFFFu, ss, off);

        const float scale = inv_S / fmaxf(sqrtf(ss), EPS_);
        #pragma unroll
        for (int c = 0; c < 6; c++) {
            acc[c].x += v[c].x * scale;
            acc[c].y += v[c].y * scale;
            acc[c].z += v[c].z * scale;
            acc[c].w += v[c].w * scale;
        }
        if (r < 7) {
            #pragma unroll
            for (int c = 0; c < 6; c++) v[c] = vn[c];
        }
    }

    #pragma unroll
    for (int c = 0; c < 6; c++)
        sm[warp * 192 + lane + 32 * c] = acc[c];
    __syncthreads();

    if (threadIdx.x < 192) {
        float4 s = sm[threadIdx.x];
        #pragma unroll
        for (int w = 1; w < 16; w++) {
            const float4 t = sm[w * 192 + threadIdx.x];
            s.x += t.x; s.y += t.y; s.z += t.z; s.w += t.w;
        }
        reinterpret_cast<float4*>(g_part)[((q * B_ + b) * 192) + threadIdx.x] = s;
    }

    __threadfence();
    __syncthreads();
    if (threadIdx.x == 0)
        is_last = (atomicAdd(&g_ticket[b], 1) == 3) ? 1 : 0;
    __syncthreads();

    if (is_last) {
        __threadfence();
        if (threadIdx.x < 192) {
            const float4* gp = reinterpret_cast<const float4*>(g_part);
            float4 a  = gp[(0 * B_ + b) * 192 + threadIdx.x];
            const float4 b4 = gp[(1 * B_ + b) * 192 + threadIdx.x];
            const float4 c4 = gp[(2 * B_ + b) * 192 + threadIdx.x];
            const float4 d4 = gp[(3 * B_ + b) * 192 + threadIdx.x];
            a.x += b4.x + c4.x + d4.x;
            a.y += b4.y + c4.y + d4.y;
            a.z += b4.z + c4.z + d4.z;
            a.w += b4.w + c4.w + d4.w;
            reinterpret_cast<float4*>(g_m)[b * 192 + threadIdx.x] = a;
        }
        if (threadIdx.x == 0) g_ticket[b] = 0;
    }
}

// ---------------------------------------------------------------------------
// Kernel 2: register-tiled GEMM, atomicAdd epilogue.
// Grid: 384 = 16 o-tiles x 24 k-splits. Block: 256 threads, 23 KB smem,
// <=85 regs (launch_bounds 256,3) -> 3 blocks/SM, 24 warps/SM, single wave.
// Warp (wb = w>>2 in 0..1, wo = w&3): tile 16b x 32o.
// Lane (bi = l>>3 in 0..3, oj = l&7): thread tile 4b x 4o.
//   b = wb*16 + bi + 4*rr (rr 0..3), o = ot*128 + wo*32 + oj + 8*ss (ss 0..3).
// Per 4-k step: 8 LDS.128 -> 32 fma2 (ratio 0.25).
// psm pre-scaled by g_rpn -> accumulators final -> atomicAdd(out).
// ---------------------------------------------------------------------------
__global__ void __launch_bounds__(256, 3)
gemm_kernel(const float* __restrict__ p, float* __restrict__ out) {
    __shared__ float msm[B_ * PM];      // 32 x 36 floats = 4.6 KB
    __shared__ float psm[OTILE * PM];   // 128 x 36 floats = 18.4 KB

    const int kq  = blockIdx.x % KSPLIT;
    const int ot  = blockIdx.x / KSPLIT;    // 0..15
    const int tid = threadIdx.x;
    const int k0  = kq * KB;

    // stage m[32][32]: 256 float4, one per thread
    {
        const int row = tid >> 3;               // 0..31
        const int col = (tid & 7) * 4;          // 0..28
        const float4 v4 = *reinterpret_cast<const float4*>(
            g_m + (size_t)row * D_ + k0 + col);
        *reinterpret_cast<float4*>(&msm[row * PM + col]) = v4;
    }
    // stage p[ot*128..+128][32] * rpn: 1024 float4, 4 per thread
    #pragma unroll
    for (int t = 0; t < 4; t++) {
        const int i   = tid + t * 256;          // 0..1023
        const int row = i >> 3;                 // 0..127
        const int col = (i & 7) * 4;
        float4 v4 = *reinterpret_cast<const float4*>(
            p + (size_t)(ot * OTILE + row) * D_ + k0 + col);
        const float rp = g_rpn[ot * OTILE + row];
        v4.x *= rp; v4.y *= rp; v4.z *= rp; v4.w *= rp;
        *reinterpret_cast<float4*>(&psm[row * PM + col]) = v4;
    }
    __syncthreads();

    const int warp = tid >> 5;
    const int lane = tid & 31;
    const int wb = warp >> 2;            // 0..1
    const int wo = warp & 3;             // 0..3
    const int bi = lane >> 3;            // 0..3
    const int oj = lane & 7;             // 0..7

    const float* mb = &msm[(wb * 16 + bi) * PM];   // + 4*rr*PM
    const float* pb = &psm[(wo * 32 + oj) * PM];   // + 8*ss*PM

    unsigned long long acc[4][4];
    #pragma unroll
    for (int rr = 0; rr < 4; rr++)
        #pragma unroll
        for (int ss = 0; ss < 4; ss++) acc[rr][ss] = 0ull;

    #pragma unroll
    for (int kk = 0; kk < 8; kk++) {
        ulonglong2 mv[4], pv[4];
        #pragma unroll
        for (int rr = 0; rr < 4; rr++)
            mv[rr] = *reinterpret_cast<const ulonglong2*>(mb + rr * 4 * PM + kk * 4);
        #pragma unroll
        for (int ss = 0; ss < 4; ss++)
            pv[ss] = *reinterpret_cast<const ulonglong2*>(pb + ss * 8 * PM + kk * 4);

        #pragma unroll
        for (int rr = 0; rr < 4; rr++)
            #pragma unroll
            for (int ss = 0; ss < 4; ss++) {
                fma2(acc[rr][ss], mv[rr].x, pv[ss].x);
                fma2(acc[rr][ss], mv[rr].y, pv[ss].y);
            }
    }

    // epilogue: accumulators already scaled by rpn -> atomicAdd into out
    #pragma unroll
    for (int rr = 0; rr < 4; rr++) {
        const int b = wb * 16 + bi + 4 * rr;
        #pragma unroll
        for (int ss = 0; ss < 4; ss++) {
            const int o = ot * OTILE + wo * 32 + oj + 8 * ss;
            atomicAdd(out + (size_t)b * O_ + o, unpack_sum(acc[rr][ss]));
        }
    }
}

// ---------------------------------------------------------------------------
extern "C" void kernel_launch(void* const* d_in, const int* in_sizes, int n_in,
                              void* d_out, int out_size) {
    const float* x = (const float*)d_in[0];   // [32, 512, 768]
    const float* p = (const float*)d_in[1];   // [2048, 768]
    float*     out = (float*)d_out;           // [32, 2048]

    (void)in_sizes; (void)n_in; (void)out_size;

    reduce_x_kernel<<<128 + 16, 512>>>(x, p, out);
    gemm_kernel<<<NOT_ * KSPLIT, 256>>>(p, out);
}